// round 5
// baseline (speedup 1.0000x reference)
#include <cuda_runtime.h>

#define N_USERS_C 200000
#define N_ITEMS_C 100000
#define N_NODES_C 300000
#define N_EDGES_C 4800000
#define EMB_C     64
#define BATCH_C   4096
#define SLOTS_C   (2 * BATCH_C)
#define N_BITWORDS ((N_NODES_C + 31) / 32)
#define MAXE      128

#define NBLK 592          // 148 SMs x 4 resident blocks (regs<=64, smem=0)
#define THR  256
#define NTHREADS (NBLK * THR)
#define NWARPS   (NTHREADS / 32)
#define NCHUNK   (N_EDGES_C / 8)

// Persistent scratch (idempotent claim state, see R3/R4 notes).
__device__ int      g_map[N_NODES_C];          // 0 = unclaimed, else slot+1 (atomicMax)
__device__ unsigned g_bits[N_BITWORDS];        // fast-reject bitmask (atomicOr)
__device__ int      g_cnt[SLOTS_C];            // per-slot edge count (re-zeroed in claim)
__device__ int2     g_data[SLOTS_C * MAXE];    // (col, val-bits) pairs

// Grid barrier state: sense-reversing, self-resetting, replay-safe
__device__ unsigned          g_barcnt = 0;
__device__ volatile unsigned g_sense  = 0;

__device__ __forceinline__ void gridbar() {
    __syncthreads();
    if (threadIdx.x == 0) {
        __threadfence();                      // publish this block's writes
        unsigned gen = g_sense;               // capture BEFORE arriving
        if (atomicAdd(&g_barcnt, 1u) == NBLK - 1) {
            g_barcnt = 0;
            __threadfence();
            g_sense = gen + 1;                // release
        } else {
            while (g_sense == gen) __nanosleep(64);
            __threadfence();                  // acquire
        }
    }
    __syncthreads();
}

__global__ void __launch_bounds__(THR, 4)
k_fused(const float* __restrict__ user_emb,
        const float* __restrict__ item_emb,
        const int*   __restrict__ adj_row,
        const int*   __restrict__ adj_col,
        const float* __restrict__ adj_vals,
        const int*   __restrict__ user_id,
        const int*   __restrict__ item_id,
        float*       __restrict__ out) {
    const int tid = blockIdx.x * THR + threadIdx.x;

    // ── Phase 1: claim ────────────────────────────────────────────────
    if (tid < SLOTS_C) {
        g_cnt[tid] = 0;
        int node = (tid < BATCH_C) ? user_id[tid]
                                   : (N_USERS_C + item_id[tid - BATCH_C]);
        atomicMax(&g_map[node], tid + 1);            // deterministic winner
        atomicOr(&g_bits[node >> 5], 1u << (node & 31));
    }
    gridbar();

    // ── Phase 2: scan (8 edges/thread/iter, grid-stride) ──────────────
    for (int c = tid; c < NCHUNK; c += NTHREADS) {
        int base = c * 8;
        int4 a = *(const int4*)(adj_row + base);     // two int4 streams in flight
        int4 b = *(const int4*)(adj_row + base + 4);
        int rr[8] = {a.x, a.y, a.z, a.w, b.x, b.y, b.z, b.w};
        #pragma unroll
        for (int k = 0; k < 8; k++) {
            int r = rr[k];
            unsigned wm = g_bits[r >> 5];            // hot 37.5KB mask
            if ((wm >> (r & 31)) & 1u) {             // ~2.7% hit rate
                int e   = base + k;
                int s   = g_map[r] - 1;
                int idx = atomicAdd(&g_cnt[s], 1);
                if (idx < MAXE)
                    g_data[s * MAXE + idx] =
                        make_int2(adj_col[e], __float_as_int(adj_vals[e]));
            }
        }
    }
    gridbar();

    // ── Phase 3: out (one warp per row, rows strided by NWARPS) ───────
    const int warp = tid >> 5;
    const int lane = tid & 31;
    for (int w = warp; w < SLOTS_C; w += NWARPS) {
        int node = (w < BATCH_C) ? user_id[w]
                                 : (N_USERS_C + item_id[w - BATCH_C]);
        const float* xrow = (node < N_USERS_C)
            ? (user_emb + (size_t)node * EMB_C)
            : (item_emb + (size_t)(node - N_USERS_C) * EMB_C);

        float2 acc = *(const float2*)(xrow + 2 * lane);  // z1 = 2*x0 + A*x0
        acc.x *= 2.0f; acc.y *= 2.0f;

        int s   = g_map[node] - 1;
        int cnt = g_cnt[s];
        if (cnt > MAXE) cnt = MAXE;
        const int2* dp = g_data + (size_t)s * MAXE;

        for (int i = 0; i < cnt; i += 8) {
            int2 d[8];
            #pragma unroll
            for (int j = 0; j < 8; j++) {            // 8 broadcast loads, unpredicated
                int k = i + j; if (k >= cnt) k = cnt - 1;
                d[j] = __ldg(&dp[k]);
                if (i + j >= cnt) d[j].y = 0;        // zero weight, keep the load
            }
            float2 xs[8];
            #pragma unroll
            for (int j = 0; j < 8; j++) {            // 8 independent gathers in flight
                int c = d[j].x;
                const float* crow = (c < N_USERS_C)
                    ? (user_emb + (size_t)c * EMB_C)
                    : (item_emb + (size_t)(c - N_USERS_C) * EMB_C);
                xs[j] = *(const float2*)(crow + 2 * lane);
            }
            #pragma unroll
            for (int j = 0; j < 8; j++) {
                float v = __int_as_float(d[j].y);
                acc.x += v * xs[j].x;
                acc.y += v * xs[j].y;
            }
        }
        *(float2*)(out + (size_t)w * EMB_C + 2 * lane) = acc;
    }
}

extern "C" void kernel_launch(void* const* d_in, const int* in_sizes, int n_in,
                              void* d_out, int out_size) {
    const float* user_emb = (const float*)d_in[0];
    const float* item_emb = (const float*)d_in[1];
    const int*   adj_row  = (const int*)  d_in[2];
    const int*   adj_col  = (const int*)  d_in[3];
    const float* adj_vals = (const float*)d_in[4];
    const int*   user_id  = (const int*)  d_in[5];
    const int*   item_id  = (const int*)  d_in[6];
    float*       out      = (float*)d_out;

    k_fused<<<NBLK, THR>>>(user_emb, item_emb, adj_row, adj_col, adj_vals,
                           user_id, item_id, out);
}